// round 7
// baseline (speedup 1.0000x reference)
#include <cuda_runtime.h>
#include <cuda_bf16.h>
#include <cstdint>

#define NPTS 80000
#define NBH  32
#define KPN  15
#define CIN  128
#define D2   64
#define COUT 256
#define FKDIM (KPN*D2)   /* 960 */
#define INV_INFL 2.5f
#define EPSBN 1e-5f
#define SLOPE 0.2f

typedef __nv_bfloat16 bf16;

/* ---------------- scratch -------------------------------------------- */
__device__ float g_x1[(size_t)NPTS*D2];        /* pre-BN unary1 (fp32 ref) */
__device__ float g_sc[(size_t)NPTS*COUT];
__device__ float g_fk[(size_t)NPTS*FKDIM];
__device__ float g_xmid[(size_t)NPTS*D2];
__device__ float g_x1t[(size_t)NPTS*D2];       /* diag: tiled HMMA unary1 */

__device__ bf16 g_feats_hi[(size_t)NPTS*CIN], g_feats_lo[(size_t)NPTS*CIN];
__device__ bf16 g_W1t_hi[D2*CIN], g_W1t_lo[D2*CIN];

__device__ float g_sum1[D2],  g_sq1[D2],  g_scale1[D2],  g_shift1[D2];
__device__ float g_sumsc[COUT],g_sqsc[COUT],g_scalesc[COUT],g_shiftsc[COUT];
__device__ float g_sum2[COUT], g_sq2[COUT], g_scale2[COUT], g_shift2[COUT];

/* ---------------- zero stats ------------------------------------------ */
__global__ void k_zero() {
    int t = threadIdx.x;
    if (t < D2) { g_sum1[t] = 0.f; g_sq1[t] = 0.f; }
    g_sumsc[t] = 0.f; g_sqsc[t] = 0.f;
    g_sum2[t]  = 0.f; g_sq2[t]  = 0.f;
}

/* ---------------- KNOWN-GOOD fp32 GEMM (R1) --------------------------- */
__device__ __forceinline__ void gemm_body(const float* __restrict__ A, int lda,
                                          const float* __restrict__ B, int ldb,
                                          float* __restrict__ C, int ldc, int Kdim)
{
    __shared__ float As[16][132];
    __shared__ float Bs[16][64];
    const int t   = threadIdx.x;
    const int m0  = blockIdx.x * 128;
    const int bn0 = blockIdx.y * 64;
    const int tx  = t & 15, ty = t >> 4;
    const int ar  = t >> 1, ac = (t & 1) * 8;
    const int br  = t >> 4, bc = (t & 15) * 4;

    float acc[8][4];
#pragma unroll
    for (int i = 0; i < 8; i++)
#pragma unroll
        for (int j = 0; j < 4; j++) acc[i][j] = 0.f;

    for (int kb = 0; kb < Kdim; kb += 16) {
        float4 a0 = *(const float4*)(A + (size_t)(m0 + ar) * lda + kb + ac);
        float4 a1 = *(const float4*)(A + (size_t)(m0 + ar) * lda + kb + ac + 4);
        float4 b0 = *(const float4*)(B + (size_t)(kb + br) * ldb + bn0 + bc);
        __syncthreads();
        As[ac+0][ar] = a0.x; As[ac+1][ar] = a0.y; As[ac+2][ar] = a0.z; As[ac+3][ar] = a0.w;
        As[ac+4][ar] = a1.x; As[ac+5][ar] = a1.y; As[ac+6][ar] = a1.z; As[ac+7][ar] = a1.w;
        *(float4*)&Bs[br][bc] = b0;
        __syncthreads();
#pragma unroll
        for (int kk = 0; kk < 16; kk++) {
            float a_[8], b_[4];
#pragma unroll
            for (int i = 0; i < 8; i++) a_[i] = As[kk][ty * 8 + i];
#pragma unroll
            for (int j = 0; j < 4; j++) b_[j] = Bs[kk][tx * 4 + j];
#pragma unroll
            for (int i = 0; i < 8; i++)
#pragma unroll
                for (int j = 0; j < 4; j++) acc[i][j] += a_[i] * b_[j];
        }
    }
#pragma unroll
    for (int i = 0; i < 8; i++) {
        float4 v = make_float4(acc[i][0], acc[i][1], acc[i][2], acc[i][3]);
        *(float4*)(C + (size_t)(m0 + ty * 8 + i) * ldc + bn0 + tx * 4) = v;
    }
}

__global__ __launch_bounds__(256) void k_gemm1(const float* A, const float* B) {
    gemm_body(A, CIN, B, D2, g_x1, D2, CIN);
}
__global__ __launch_bounds__(256) void k_gemmsc(const float* A, const float* B) {
    gemm_body(A, CIN, B, COUT, g_sc, COUT, CIN);
}
__global__ __launch_bounds__(256) void k_gemmfk(const float* B) {
    gemm_body(g_fk, FKDIM, B, D2, g_xmid, D2, FKDIM);
}
__global__ __launch_bounds__(256) void k_gemm2(const float* B, float* C) {
    gemm_body(g_xmid, D2, B, COUT, C, COUT, D2);
}

/* ---------------- stats / fin (known good) ----------------------------- */
template <int C>
__device__ __forceinline__ void stats_body(const float* __restrict__ X,
                                           float* sum, float* sq)
{
    constexpr int REPS = 256 / C;
    const int t = threadIdx.x;
    const int c = t % C;
    const int rep = t / C;
    float s = 0.f, s2 = 0.f;
    for (int r = blockIdx.x * REPS + rep; r < NPTS; r += gridDim.x * REPS) {
        float v = X[(size_t)r * C + c];
        s += v; s2 += v * v;
    }
    atomicAdd(&sum[c], s);
    atomicAdd(&sq[c], s2);
}
__global__ void k_stats1()               { stats_body<D2>(g_x1, g_sum1, g_sq1); }
__global__ void k_statssc()              { stats_body<COUT>(g_sc, g_sumsc, g_sqsc); }
__global__ void k_stats2(const float* X) { stats_body<COUT>(X, g_sum2, g_sq2); }

__device__ __forceinline__ void fin_body(const float* sum, const float* sq,
                                         const float* g, const float* b,
                                         float* scale, float* shift)
{
    int c = threadIdx.x;
    float m = sum[c] * (1.0f / NPTS);
    float v = sq[c] * (1.0f / NPTS) - m * m;
    float s = g[c] * rsqrtf(v + EPSBN);
    scale[c] = s;
    shift[c] = b[c] - m * s;
}
__global__ void k_fin1(const float* g, const float* b)  { fin_body(g_sum1, g_sq1, g, b, g_scale1, g_shift1); }
__global__ void k_finsc(const float* g, const float* b) { fin_body(g_sumsc, g_sqsc, g, b, g_scalesc, g_shiftsc); }
__global__ void k_fin2(const float* g, const float* b)  { fin_body(g_sum2, g_sq2, g, b, g_scale2, g_shift2); }

/* ---------------- KPConv (R1 known good) ------------------------------- */
__device__ __forceinline__ float fsqrt_approx(float x) {
    float r; asm("sqrt.approx.f32 %0, %1;" : "=f"(r) : "f"(x)); return r;
}

__global__ __launch_bounds__(256) void k_kpconv(const float* __restrict__ xyz,
                                                const int* __restrict__ nidx,
                                                const float* __restrict__ kp)
{
    __shared__ float kps[KPN][3];
    __shared__ float ws[8][NBH][KPN];
    const int t = threadIdx.x;
    if (t < KPN * 3) ((float*)kps)[t] = kp[t];
    __syncthreads();

    const int warp = t >> 5, lane = t & 31;
    const int n = blockIdx.x * 8 + warp;

    const float cx = xyz[n * 3 + 0], cy = xyz[n * 3 + 1], cz = xyz[n * 3 + 2];
    const int j = nidx[n * NBH + lane];
    const float rx = xyz[j * 3 + 0] - cx;
    const float ry = xyz[j * 3 + 1] - cy;
    const float rz = xyz[j * 3 + 2] - cz;

#pragma unroll
    for (int k = 0; k < KPN; k++) {
        float dx = rx - kps[k][0], dy = ry - kps[k][1], dz = rz - kps[k][2];
        float sq = dx * dx + dy * dy + dz * dz;
        float w = 1.0f - fsqrt_approx(sq) * INV_INFL;
        ws[warp][lane][k] = w > 0.f ? w : 0.f;
    }
    __syncwarp();

    const float sc0 = g_scale1[2 * lane],     sc1 = g_scale1[2 * lane + 1];
    const float sh0 = g_shift1[2 * lane],     sh1 = g_shift1[2 * lane + 1];
    float fk0[KPN], fk1[KPN];
#pragma unroll
    for (int k = 0; k < KPN; k++) { fk0[k] = 0.f; fk1[k] = 0.f; }

    const float2* x1v = (const float2*)g_x1;
#pragma unroll 4
    for (int h = 0; h < NBH; h++) {
        int jj = __shfl_sync(0xffffffffu, j, h);
        float2 v = x1v[(size_t)jj * 32 + lane];
        float a = v.x * sc0 + sh0; a = a > 0.f ? a : SLOPE * a;
        float b = v.y * sc1 + sh1; b = b > 0.f ? b : SLOPE * b;
#pragma unroll
        for (int k = 0; k < KPN; k++) {
            float w = ws[warp][h][k];
            fk0[k] += w * a;
            fk1[k] += w * b;
        }
    }

    float2* out = (float2*)(g_fk + (size_t)n * FKDIM);
#pragma unroll
    for (int k = 0; k < KPN; k++)
        out[k * 32 + lane] = make_float2(fk0[k], fk1[k]);
}

/* ---------------- epilogue (R1 known good) ------------------------------ */
__global__ __launch_bounds__(256) void k_epilogue(float* __restrict__ out)
{
    __shared__ float s2[COUT], h2[COUT], ss[COUT], hs[COUT];
    const int t = threadIdx.x;
    s2[t] = g_scale2[t];  h2[t] = g_shift2[t];
    ss[t] = g_scalesc[t]; hs[t] = g_shiftsc[t];
    __syncthreads();

    const int idx = blockIdx.x * 256 + t;
    const int c4 = (idx & 63) * 4;

    float4 x = ((float4*)out)[idx];
    float4 s = ((const float4*)g_sc)[idx];
    float v0 = x.x * s2[c4 + 0] + h2[c4 + 0]; v0 = v0 > 0.f ? v0 : SLOPE * v0;
    float v1 = x.y * s2[c4 + 1] + h2[c4 + 1]; v1 = v1 > 0.f ? v1 : SLOPE * v1;
    float v2 = x.z * s2[c4 + 2] + h2[c4 + 2]; v2 = v2 > 0.f ? v2 : SLOPE * v2;
    float v3 = x.w * s2[c4 + 3] + h2[c4 + 3]; v3 = v3 > 0.f ? v3 : SLOPE * v3;
    float4 r;
    r.x = v0 + s.x * ss[c4 + 0] + hs[c4 + 0];
    r.y = v1 + s.y * ss[c4 + 1] + hs[c4 + 1];
    r.z = v2 + s.z * ss[c4 + 2] + hs[c4 + 2];
    r.w = v3 + s.w * ss[c4 + 3] + hs[c4 + 3];
    ((float4*)out)[idx] = r;
}

/* ======================= DIAGNOSTIC SECTION ============================ */
__global__ __launch_bounds__(256) void k_prep_feats(const float* __restrict__ f) {
    int i4 = blockIdx.x * 256 + threadIdx.x;
    float4 v = ((const float4*)f)[i4];
    bf16 h0 = __float2bfloat16(v.x), h1 = __float2bfloat16(v.y);
    bf16 h2 = __float2bfloat16(v.z), h3 = __float2bfloat16(v.w);
    union { bf16 b[4]; uint2 u; } H, L;
    H.b[0] = h0; H.b[1] = h1; H.b[2] = h2; H.b[3] = h3;
    L.b[0] = __float2bfloat16(v.x - __bfloat162float(h0));
    L.b[1] = __float2bfloat16(v.y - __bfloat162float(h1));
    L.b[2] = __float2bfloat16(v.z - __bfloat162float(h2));
    L.b[3] = __float2bfloat16(v.w - __bfloat162float(h3));
    ((uint2*)g_feats_hi)[i4] = H.u;
    ((uint2*)g_feats_lo)[i4] = L.u;
}

__global__ void k_prep_w1(const float* __restrict__ W1) {
    int i = blockIdx.x * 256 + threadIdx.x;   /* < 8192 */
    int e = i >> 7, k = i & 127;
    float v = W1[k * D2 + e];
    bf16 h = __float2bfloat16(v);
    g_W1t_hi[i] = h;
    g_W1t_lo[i] = __float2bfloat16(v - __bfloat162float(h));
}

__device__ __forceinline__ void mma16816(float* c, const uint32_t* a, const uint32_t* b) {
    asm volatile("mma.sync.aligned.m16n8k16.row.col.f32.bf16.bf16.f32 "
        "{%0,%1,%2,%3}, {%4,%5,%6,%7}, {%8,%9}, {%0,%1,%2,%3};"
        : "+f"(c[0]), "+f"(c[1]), "+f"(c[2]), "+f"(c[3])
        : "r"(a[0]), "r"(a[1]), "r"(a[2]), "r"(a[3]), "r"(b[0]), "r"(b[1]));
}
__device__ __forceinline__ uint32_t ld32s(const bf16* p) {
    return *reinterpret_cast<const uint32_t*>(p);
}
__device__ __forceinline__ float clampd(float d, float cap) {
    float m = fminf(fabsf(d), cap);
    return copysignf(m, d);
}

/* --- ch1: the EXACT R6 tiled HMMA GEMM, unary1 shape, -> g_x1t --------- */
#define AST 40
__global__ __launch_bounds__(256) void k_mma_diag_tiled()
{
    __shared__ __align__(16) bf16 sAh[128 * AST];
    __shared__ __align__(16) bf16 sAl[128 * AST];
    __shared__ __align__(16) bf16 sBh[64 * AST];
    __shared__ __align__(16) bf16 sBl[64 * AST];

    const bf16* Ahi = g_feats_hi; const bf16* Alo = g_feats_lo;
    const bf16* Bhi = g_W1t_hi;   const bf16* Blo = g_W1t_lo;
    constexpr int KTOT = 128;

    const int t = threadIdx.x, lane = t & 31, wid = t >> 5;
    const int wm = wid & 3, wn = wid >> 2;
    const int m0 = blockIdx.x * 128, n0 = 0;
    const int gr = lane >> 2, gc2 = (lane & 3) * 2;

    float acc[2][4][4];
#pragma unroll
    for (int i = 0; i < 2; i++)
#pragma unroll
        for (int j = 0; j < 4; j++)
#pragma unroll
            for (int q = 0; q < 4; q++) acc[i][j][q] = 0.f;

    constexpr int NCH = KTOT / 32;
    for (int kc = 0; kc < NCH; kc++) {
        __syncthreads();
#pragma unroll
        for (int it = 0; it < 2; it++) {
            int v = t + it * 256;
            int row = v >> 2, c8 = (v & 3) * 8;
            size_t gsrc = (size_t)(m0 + row) * KTOT + kc * 32 + c8;
            *(uint4*)(sAh + row * AST + c8) = *(const uint4*)(Ahi + gsrc);
            *(uint4*)(sAl + row * AST + c8) = *(const uint4*)(Alo + gsrc);
        }
        {
            int row = t >> 2, c8 = (t & 3) * 8;
            size_t gsrc = (size_t)(n0 + row) * KTOT + kc * 32 + c8;
            *(uint4*)(sBh + row * AST + c8) = *(const uint4*)(Bhi + gsrc);
            *(uint4*)(sBl + row * AST + c8) = *(const uint4*)(Blo + gsrc);
        }
        __syncthreads();

#pragma unroll
        for (int kk = 0; kk < 2; kk++) {
            const int kb = kk * 16;
            uint32_t ah[2][4], al[2][4], bh[4][2], bl[4][2];
#pragma unroll
            for (int mt = 0; mt < 2; mt++) {
                const bf16* ph = sAh + (wm * 32 + mt * 16 + gr) * AST + kb + gc2;
                ah[mt][0] = ld32s(ph);
                ah[mt][1] = ld32s(ph + 8 * AST);
                ah[mt][2] = ld32s(ph + 8);
                ah[mt][3] = ld32s(ph + 8 * AST + 8);
                const bf16* pl = sAl + (wm * 32 + mt * 16 + gr) * AST + kb + gc2;
                al[mt][0] = ld32s(pl);
                al[mt][1] = ld32s(pl + 8 * AST);
                al[mt][2] = ld32s(pl + 8);
                al[mt][3] = ld32s(pl + 8 * AST + 8);
            }
#pragma unroll
            for (int nt = 0; nt < 4; nt++) {
                const bf16* ph = sBh + (wn * 32 + nt * 8 + gr) * AST + kb + gc2;
                bh[nt][0] = ld32s(ph);
                bh[nt][1] = ld32s(ph + 8);
                const bf16* pl = sBl + (wn * 32 + nt * 8 + gr) * AST + kb + gc2;
                bl[nt][0] = ld32s(pl);
                bl[nt][1] = ld32s(pl + 8);
            }
#pragma unroll
            for (int mt = 0; mt < 2; mt++)
#pragma unroll
                for (int nt = 0; nt < 4; nt++) {
                    mma16816(acc[mt][nt], ah[mt], bh[nt]);
                    mma16816(acc[mt][nt], ah[mt], bl[nt]);
                    mma16816(acc[mt][nt], al[mt], bh[nt]);
                }
        }
    }

    const int rbase = m0 + wm * 32 + gr;
    const int cbase = wn * 32 + gc2;
#pragma unroll
    for (int mt = 0; mt < 2; mt++)
#pragma unroll
        for (int nt = 0; nt < 4; nt++) {
            int r0 = rbase + mt * 16, r1 = r0 + 8;
            int cc = n0 + cbase + nt * 8;
            *(float2*)(g_x1t + (size_t)r0 * D2 + cc) =
                make_float2(acc[mt][nt][0], acc[mt][nt][1]);
            *(float2*)(g_x1t + (size_t)r1 * D2 + cc) =
                make_float2(acc[mt][nt][2], acc[mt][nt][3]);
        }
}

/* ch1 inject: out[n][c] += 0.2*clamp(x1t-x1, 1e-3), c in [0,64) */
__global__ __launch_bounds__(256) void k_diff_tiled(float* __restrict__ out)
{
    int i = blockIdx.x * 256 + threadIdx.x;      /* < NPTS*D2 */
    int n = i >> 6, c = i & 63;
    float d = g_x1t[i] - g_x1[i];
    out[(size_t)n * COUT + c] += 0.2f * clampd(d, 1e-3f);
}

/* --- ch2: minimal warp HMMA straight from global (no smem) ------------- */
/* grid (512, 8): rows m0=16*bx (<8192), cols n0=8*by. K=128. */
__global__ __launch_bounds__(32) void k_diag_simple(float* __restrict__ out)
{
    const int lane = threadIdx.x;
    const int gr = lane >> 2, gc2 = (lane & 3) * 2;
    const int m0 = blockIdx.x * 16, n0 = blockIdx.y * 8;

    float acc[4] = {0.f, 0.f, 0.f, 0.f};
#pragma unroll
    for (int kk = 0; kk < 8; kk++) {
        const int kb = kk * 16;
        uint32_t ah[4], al[4], bh[2], bl[2];
        const bf16* pa = g_feats_hi + (size_t)(m0 + gr) * CIN + kb + gc2;
        ah[0] = ld32s(pa);
        ah[1] = ld32s(pa + 8 * CIN);
        ah[2] = ld32s(pa + 8);
        ah[3] = ld32s(pa + 8 * CIN + 8);
        const bf16* pal = g_feats_lo + (size_t)(m0 + gr) * CIN + kb + gc2;
        al[0] = ld32s(pal);
        al[1] = ld32s(pal + 8 * CIN);
        al[2] = ld32s(pal + 8);
        al[3] = ld32s(pal + 8 * CIN + 8);
        const bf16* pb = g_W1t_hi + (size_t)(n0 + gr) * CIN + kb + gc2;
        bh[0] = ld32s(pb);
        bh[1] = ld32s(pb + 8);
        const bf16* pbl = g_W1t_lo + (size_t)(n0 + gr) * CIN + kb + gc2;
        bl[0] = ld32s(pbl);
        bl[1] = ld32s(pbl + 8);

        mma16816(acc, ah, bh);
        mma16816(acc, ah, bl);
        mma16816(acc, al, bh);
    }

    /* c0,c1 -> (m0+gr, n0+gc2(+1)); c2,c3 -> (m0+gr+8, ...) */
    int r0 = m0 + gr, r1 = r0 + 8;
    int c0 = n0 + gc2;
    float d00 = acc[0] - g_x1[(size_t)r0 * D2 + c0];
    float d01 = acc[1] - g_x1[(size_t)r0 * D2 + c0 + 1];
    float d10 = acc[2] - g_x1[(size_t)r1 * D2 + c0];
    float d11 = acc[3] - g_x1[(size_t)r1 * D2 + c0 + 1];
    out[(size_t)r0 * COUT + 64 + c0]     += 0.45f * clampd(d00, 1e-3f);
    out[(size_t)r0 * COUT + 64 + c0 + 1] += 0.45f * clampd(d01, 1e-3f);
    out[(size_t)r1 * COUT + 64 + c0]     += 0.45f * clampd(d10, 1e-3f);
    out[(size_t)r1 * COUT + 64 + c0 + 1] += 0.45f * clampd(d11, 1e-3f);
}

/* ---------------- launch ------------------------------------------------ */
extern "C" void kernel_launch(void* const* d_in, const int* in_sizes, int n_in,
                              void* d_out, int out_size)
{
    const float* feats = (const float*)d_in[0];
    const float* xyz   = (const float*)d_in[1];
    const int*   nidx  = (const int*)d_in[3];
    const float* W1    = (const float*)d_in[4];
    const float* g1    = (const float*)d_in[5];
    const float* b1    = (const float*)d_in[6];
    const float* kp    = (const float*)d_in[7];
    const float* kpw   = (const float*)d_in[8];
    const float* W2    = (const float*)d_in[9];
    const float* g2    = (const float*)d_in[10];
    const float* b2    = (const float*)d_in[11];
    const float* Wsc   = (const float*)d_in[12];
    const float* gsc   = (const float*)d_in[13];
    const float* bsc   = (const float*)d_in[14];
    float* out = (float*)d_out;

    k_zero<<<1, 256>>>();
    k_prep_feats<<<(NPTS * CIN / 4) / 256, 256>>>(feats);
    k_prep_w1<<<32, 256>>>(W1);

    /* ---- known-good fp32 pipeline (produces the real output) ---- */
    k_gemm1 <<<dim3(NPTS / 128, 1), 256>>>(feats, W1);
    k_gemmsc<<<dim3(NPTS / 128, 4), 256>>>(feats, Wsc);

    k_stats1 <<<512, 256>>>();
    k_statssc<<<512, 256>>>();
    k_fin1 <<<1, D2>>>(g1, b1);
    k_finsc<<<1, COUT>>>(gsc, bsc);

    k_kpconv<<<NPTS / 8, 256>>>(xyz, nidx, kp);

    k_gemmfk<<<dim3(NPTS / 128, 1), 256>>>(kpw);
    k_gemm2 <<<dim3(NPTS / 128, 4), 256>>>(W2, out);

    k_stats2<<<512, 256>>>(out);
    k_fin2<<<1, COUT>>>(g2, b2);

    k_epilogue<<<(NPTS * (COUT / 4)) / 256, 256>>>(out);

    /* ---- diagnostics: perturb out by clamped HMMA-vs-fp32 deltas ---- */
    k_mma_diag_tiled<<<NPTS / 128, 256>>>();
    k_diff_tiled<<<(NPTS * D2) / 256, 256>>>(out);
    k_diag_simple<<<dim3(512, 8), 32>>>(out);
}

// round 8
// speedup vs baseline: 1.2483x; 1.2483x over previous
#include <cuda_runtime.h>
#include <cuda_bf16.h>
#include <cstdint>

#define NPTS 80000
#define NBH  32
#define KPN  15
#define CIN  128
#define D2   64
#define COUT 256
#define FKDIM (KPN*D2)   /* 960 */
#define INV_INFL 2.5f
#define EPSBN 1e-5f
#define SLOPE 0.2f

typedef __nv_bfloat16 bf16;

/* ------------------------- device scratch ------------------------------- */
/* NOTE: these are referenced ONLY from device code. Passing a __device__
   global as a host-side kernel argument silently passes the host shadow
   address (ATS on GB300 makes it readable/writable!) — that was the R4-R6
   rel_err=1.0 bug. */
__device__ float g_x1[(size_t)NPTS*D2];
__device__ float g_sc[(size_t)NPTS*COUT];
__device__ bf16  g_feats_hi[(size_t)NPTS*CIN], g_feats_lo[(size_t)NPTS*CIN];
__device__ bf16  g_fk_hi[(size_t)NPTS*FKDIM], g_fk_lo[(size_t)NPTS*FKDIM];
__device__ bf16  g_xmid_hi[(size_t)NPTS*D2],  g_xmid_lo[(size_t)NPTS*D2];

__device__ bf16 g_W1t_hi[D2*CIN],   g_W1t_lo[D2*CIN];
__device__ bf16 g_Wsct_hi[COUT*CIN],g_Wsct_lo[COUT*CIN];
__device__ bf16 g_kpwt_hi[D2*FKDIM],g_kpwt_lo[D2*FKDIM];
__device__ bf16 g_W2t_hi[COUT*D2],  g_W2t_lo[COUT*D2];

__device__ float g_sum1[D2],  g_sq1[D2],  g_scale1[D2],  g_shift1[D2];
__device__ float g_sumsc[COUT],g_sqsc[COUT],g_scalesc[COUT],g_shiftsc[COUT];
__device__ float g_sum2[COUT], g_sq2[COUT], g_scale2[COUT], g_shift2[COUT];

/* ------------------------- ptx helpers ---------------------------------- */
__device__ __forceinline__ void mma16816(float* c, const uint32_t* a, const uint32_t* b) {
    asm volatile("mma.sync.aligned.m16n8k16.row.col.f32.bf16.bf16.f32 "
        "{%0,%1,%2,%3}, {%4,%5,%6,%7}, {%8,%9}, {%0,%1,%2,%3};"
        : "+f"(c[0]), "+f"(c[1]), "+f"(c[2]), "+f"(c[3])
        : "r"(a[0]), "r"(a[1]), "r"(a[2]), "r"(a[3]), "r"(b[0]), "r"(b[1]));
}
__device__ __forceinline__ uint32_t ld32s(const bf16* p) {
    return *reinterpret_cast<const uint32_t*>(p);
}

/* ------------------------- misc small kernels --------------------------- */
__global__ void k_zero() {
    int t = threadIdx.x;
    if (t < D2) { g_sum1[t] = 0.f; g_sq1[t] = 0.f; }
    g_sumsc[t] = 0.f; g_sqsc[t] = 0.f;
    g_sum2[t]  = 0.f; g_sq2[t]  = 0.f;
}

__device__ __forceinline__ void split_store(float v, bf16* hi, bf16* lo, size_t i) {
    bf16 h = __float2bfloat16(v);
    hi[i] = h;
    lo[i] = __float2bfloat16(v - __bfloat162float(h));
}

__global__ __launch_bounds__(256) void k_prep_feats(const float* __restrict__ f) {
    int i4 = blockIdx.x * 256 + threadIdx.x;            /* < 2,560,000 */
    float4 v = ((const float4*)f)[i4];
    bf16 h0 = __float2bfloat16(v.x), h1 = __float2bfloat16(v.y);
    bf16 h2 = __float2bfloat16(v.z), h3 = __float2bfloat16(v.w);
    union { bf16 b[4]; uint2 u; } H, L;
    H.b[0] = h0; H.b[1] = h1; H.b[2] = h2; H.b[3] = h3;
    L.b[0] = __float2bfloat16(v.x - __bfloat162float(h0));
    L.b[1] = __float2bfloat16(v.y - __bfloat162float(h1));
    L.b[2] = __float2bfloat16(v.z - __bfloat162float(h2));
    L.b[3] = __float2bfloat16(v.w - __bfloat162float(h3));
    ((uint2*)g_feats_hi)[i4] = H.u;
    ((uint2*)g_feats_lo)[i4] = L.u;
}

__global__ __launch_bounds__(256) void k_prep_w(const float* __restrict__ W1,
                                                const float* __restrict__ Wsc,
                                                const float* __restrict__ kpw,
                                                const float* __restrict__ W2)
{
    int i = blockIdx.x * 256 + threadIdx.x;             /* < 118784 */
    if (i < 8192) {                                     /* W1t [64,128] */
        int e = i >> 7, k = i & 127;
        split_store(W1[k * D2 + e], g_W1t_hi, g_W1t_lo, i);
    } else if (i < 40960) {                             /* Wsct [256,128] */
        int j = i - 8192; int e = j >> 7, k = j & 127;
        split_store(Wsc[k * COUT + e], g_Wsct_hi, g_Wsct_lo, j);
    } else if (i < 102400) {                            /* kpwt [64,960] */
        int j = i - 40960; int e = j / FKDIM, kd = j % FKDIM;
        split_store(kpw[(size_t)kd * D2 + e], g_kpwt_hi, g_kpwt_lo, j);
    } else {                                            /* W2t [256,64] */
        int j = i - 102400; int e = j >> 6, k = j & 63;
        split_store(W2[k * COUT + e], g_W2t_hi, g_W2t_lo, j);
    }
}

/* ---------------- channel stats (sum / sumsq over N) — known good ------- */
template <int C>
__device__ __forceinline__ void stats_body(const float* __restrict__ X,
                                           float* sum, float* sq)
{
    constexpr int REPS = 256 / C;
    const int t = threadIdx.x;
    const int c = t % C;
    const int rep = t / C;
    float s = 0.f, s2 = 0.f;
    for (int r = blockIdx.x * REPS + rep; r < NPTS; r += gridDim.x * REPS) {
        float v = X[(size_t)r * C + c];
        s += v; s2 += v * v;
    }
    atomicAdd(&sum[c], s);
    atomicAdd(&sq[c], s2);
}
__global__ void k_stats1()               { stats_body<D2>(g_x1, g_sum1, g_sq1); }
__global__ void k_statssc()              { stats_body<COUT>(g_sc, g_sumsc, g_sqsc); }
__global__ void k_stats2(const float* X) { stats_body<COUT>(X, g_sum2, g_sq2); }

__device__ __forceinline__ void fin_body(const float* sum, const float* sq,
                                         const float* g, const float* b,
                                         float* scale, float* shift)
{
    int c = threadIdx.x;
    float m = sum[c] * (1.0f / NPTS);
    float v = sq[c] * (1.0f / NPTS) - m * m;
    float s = g[c] * rsqrtf(v + EPSBN);
    scale[c] = s;
    shift[c] = b[c] - m * s;
}
__global__ void k_fin1(const float* g, const float* b)  { fin_body(g_sum1, g_sq1, g, b, g_scale1, g_shift1); }
__global__ void k_finsc(const float* g, const float* b) { fin_body(g_sumsc, g_sqsc, g, b, g_scalesc, g_shiftsc); }
__global__ void k_fin2(const float* g, const float* b)  { fin_body(g_sum2, g_sq2, g, b, g_scale2, g_shift2); }

/* ------------------------- HMMA split-bf16 GEMM (VERIFIED R7) ------------ */
/* Tile 128x64, 256 thr = 8 warps (4 m x 2 n), warp tile 32x32.
   Direct 32-bit LDS fragment loads at canonical m16n8k16 lane coords.
   Row stride AST=40 bf16 (80 B): banks (20*row + c) mod 32 conflict-free.
   D = Ah*Bh + Ah*Bl + Al*Bh (fp32 accum).
   MODE 0: fp32 C.  MODE 1: split bf16 hi/lo C (ld 64). */
#define AST 40

template<int KTOT, int MODE>
__device__ __forceinline__ void mmagemm_body(
    const bf16* __restrict__ Ahi, const bf16* __restrict__ Alo,
    const bf16* __restrict__ Bhi, const bf16* __restrict__ Blo,
    float* __restrict__ Cf, int ldc,
    bf16* __restrict__ Chi, bf16* __restrict__ Clo)
{
    __shared__ __align__(16) bf16 sAh[128 * AST];
    __shared__ __align__(16) bf16 sAl[128 * AST];
    __shared__ __align__(16) bf16 sBh[64 * AST];
    __shared__ __align__(16) bf16 sBl[64 * AST];

    const int t = threadIdx.x, lane = t & 31, wid = t >> 5;
    const int wm = wid & 3, wn = wid >> 2;
    const int m0 = blockIdx.x * 128, n0 = blockIdx.y * 64;
    const int gr = lane >> 2, gc2 = (lane & 3) * 2;

    float acc[2][4][4];
#pragma unroll
    for (int i = 0; i < 2; i++)
#pragma unroll
        for (int j = 0; j < 4; j++)
#pragma unroll
            for (int q = 0; q < 4; q++) acc[i][j][q] = 0.f;

    constexpr int NCH = KTOT / 32;
    for (int kc = 0; kc < NCH; kc++) {
        __syncthreads();
#pragma unroll
        for (int it = 0; it < 2; it++) {
            int v = t + it * 256;
            int row = v >> 2, c8 = (v & 3) * 8;
            size_t gsrc = (size_t)(m0 + row) * KTOT + kc * 32 + c8;
            *(uint4*)(sAh + row * AST + c8) = *(const uint4*)(Ahi + gsrc);
            *(uint4*)(sAl + row * AST + c8) = *(const uint4*)(Alo + gsrc);
        }
        {
            int row = t >> 2, c8 = (t & 3) * 8;
            size_t gsrc = (size_t)(n0 + row) * KTOT + kc * 32 + c8;
            *(uint4*)(sBh + row * AST + c8) = *(const uint4*)(Bhi + gsrc);
            *(uint4*)(sBl + row * AST + c8) = *(const uint4*)(Blo + gsrc);
        }
        __syncthreads();

#pragma unroll
        for (int kk = 0; kk < 2; kk++) {
            const int kb = kk * 16;
            uint32_t ah[2][4], al[2][4], bh[4][2], bl[4][2];
#pragma unroll
            for (int mt = 0; mt < 2; mt++) {
                const bf16* ph = sAh + (wm * 32 + mt * 16 + gr) * AST + kb + gc2;
                ah[mt][0] = ld32s(ph);
                ah[mt][1] = ld32s(ph + 8 * AST);
                ah[mt][2] = ld32s(ph + 8);
                ah[mt][3] = ld32s(ph + 8 * AST + 8);
                const bf16* pl = sAl + (wm * 32 + mt * 16 + gr) * AST + kb + gc2;
                al[mt][0] = ld32s(pl);
                al[mt][1] = ld32s(pl + 8 * AST);
                al[mt][2] = ld32s(pl + 8);
                al[mt][3] = ld32s(pl + 8 * AST + 8);
            }
#pragma unroll
            for (int nt = 0; nt < 4; nt++) {
                const bf16* ph = sBh + (wn * 32 + nt * 8 + gr) * AST + kb + gc2;
                bh[nt][0] = ld32s(ph);
                bh[nt][1] = ld32s(ph + 8);
                const bf16* pl = sBl + (wn * 32 + nt * 8 + gr) * AST + kb + gc2;
                bl[nt][0] = ld32s(pl);
                bl[nt][1] = ld32s(pl + 8);
            }
#pragma unroll
            for (int mt = 0; mt < 2; mt++)
#pragma unroll
                for (int nt = 0; nt < 4; nt++) {
                    mma16816(acc[mt][nt], ah[mt], bh[nt]);
                    mma16816(acc[mt][nt], ah[mt], bl[nt]);
                    mma16816(acc[mt][nt], al[mt], bh[nt]);
                }
        }
    }

    const int rbase = m0 + wm * 32 + gr;
    const int cbase = wn * 32 + gc2;

    if (MODE == 0) {
#pragma unroll
        for (int mt = 0; mt < 2; mt++)
#pragma unroll
            for (int nt = 0; nt < 4; nt++) {
                int r0 = rbase + mt * 16, r1 = r0 + 8;
                int cc = n0 + cbase + nt * 8;
                *(float2*)(Cf + (size_t)r0 * ldc + cc) =
                    make_float2(acc[mt][nt][0], acc[mt][nt][1]);
                *(float2*)(Cf + (size_t)r1 * ldc + cc) =
                    make_float2(acc[mt][nt][2], acc[mt][nt][3]);
            }
    } else {
#pragma unroll
        for (int mt = 0; mt < 2; mt++)
#pragma unroll
            for (int nt = 0; nt < 4; nt++) {
                int cc = n0 + cbase + nt * 8;
#pragma unroll
                for (int half = 0; half < 2; half++) {
                    int rr = rbase + mt * 16 + half * 8;
                    float v0 = acc[mt][nt][half * 2 + 0];
                    float v1 = acc[mt][nt][half * 2 + 1];
                    union { bf16 b[2]; uint32_t u; } H, L;
                    bf16 h0 = __float2bfloat16(v0), h1 = __float2bfloat16(v1);
                    H.b[0] = h0; H.b[1] = h1;
                    L.b[0] = __float2bfloat16(v0 - __bfloat162float(h0));
                    L.b[1] = __float2bfloat16(v1 - __bfloat162float(h1));
                    *(uint32_t*)(Chi + (size_t)rr * 64 + cc) = H.u;
                    *(uint32_t*)(Clo + (size_t)rr * 64 + cc) = L.u;
                }
            }
    }
}

/* wrappers: globals bound in DEVICE code */
__global__ __launch_bounds__(256) void k_gemm_u1() {
    mmagemm_body<128, 0>(g_feats_hi, g_feats_lo, g_W1t_hi, g_W1t_lo,
                         g_x1, D2, nullptr, nullptr);
}
__global__ __launch_bounds__(256) void k_gemm_sc() {
    mmagemm_body<128, 0>(g_feats_hi, g_feats_lo, g_Wsct_hi, g_Wsct_lo,
                         g_sc, COUT, nullptr, nullptr);
}
__global__ __launch_bounds__(256) void k_gemm_fk() {
    mmagemm_body<960, 1>(g_fk_hi, g_fk_lo, g_kpwt_hi, g_kpwt_lo,
                         nullptr, 0, g_xmid_hi, g_xmid_lo);
}
__global__ __launch_bounds__(256) void k_gemm_u2(float* __restrict__ out) {
    mmagemm_body<64, 0>(g_xmid_hi, g_xmid_lo, g_W2t_hi, g_W2t_lo,
                        out, COUT, nullptr, nullptr);
}

/* ------------------------- KPConv (sparse influence) -------------------- */
__device__ __forceinline__ float fsqrt_approx(float x) {
    float r; asm("sqrt.approx.f32 %0, %1;" : "=f"(r) : "f"(x)); return r;
}

__global__ __launch_bounds__(256) void k_kpconv(const float* __restrict__ xyz,
                                                const int* __restrict__ nidx,
                                                const float* __restrict__ kp)
{
    __shared__ float kps[KPN][3];
    __shared__ float ws[8][NBH][KPN];
    const int t = threadIdx.x;
    if (t < KPN * 3) ((float*)kps)[t] = kp[t];
    __syncthreads();

    const int warp = t >> 5, lane = t & 31;
    const int n = blockIdx.x * 8 + warp;

    const float cx = xyz[n * 3 + 0], cy = xyz[n * 3 + 1], cz = xyz[n * 3 + 2];
    const int j = nidx[n * NBH + lane];
    const float rx = xyz[j * 3 + 0] - cx;
    const float ry = xyz[j * 3 + 1] - cy;
    const float rz = xyz[j * 3 + 2] - cz;

    unsigned mask = 0;
#pragma unroll
    for (int k = 0; k < KPN; k++) {
        float dx = rx - kps[k][0], dy = ry - kps[k][1], dz = rz - kps[k][2];
        float sq = dx * dx + dy * dy + dz * dz;
        float w = 1.0f - fsqrt_approx(sq) * INV_INFL;
        w = w > 0.f ? w : 0.f;
        ws[warp][lane][k] = w;
        if (w > 0.f) mask |= (1u << k);
    }
    __syncwarp();

    const float sc0 = g_scale1[2 * lane], sc1 = g_scale1[2 * lane + 1];
    const float sh0 = g_shift1[2 * lane], sh1 = g_shift1[2 * lane + 1];
    const float2* x1v = (const float2*)g_x1;

    float fk0[KPN], fk1[KPN];
#pragma unroll
    for (int k = 0; k < KPN; k++) { fk0[k] = 0.f; fk1[k] = 0.f; }

    for (int h = 0; h < NBH; h++) {
        unsigned mh = __shfl_sync(0xffffffffu, mask, h);
        if (!mh) continue;                                 /* warp-uniform */
        int jj = __shfl_sync(0xffffffffu, j, h);
        float2 v = x1v[(size_t)jj * 32 + lane];
        float a = v.x * sc0 + sh0; a = a > 0.f ? a : SLOPE * a;
        float b = v.y * sc1 + sh1; b = b > 0.f ? b : SLOPE * b;
        while (mh) {
            int k = __ffs(mh) - 1; mh &= mh - 1;
            float w = ws[warp][h][k];
            fk0[k] += w * a;
            fk1[k] += w * b;
        }
    }

    bf16* oh = g_fk_hi + (size_t)n * FKDIM;
    bf16* ol = g_fk_lo + (size_t)n * FKDIM;
#pragma unroll
    for (int k = 0; k < KPN; k++) {
        union { bf16 b[2]; uint32_t u; } H, L;
        bf16 h0 = __float2bfloat16(fk0[k]), h1 = __float2bfloat16(fk1[k]);
        H.b[0] = h0; H.b[1] = h1;
        L.b[0] = __float2bfloat16(fk0[k] - __bfloat162float(h0));
        L.b[1] = __float2bfloat16(fk1[k] - __bfloat162float(h1));
        *(uint32_t*)(oh + k * 64 + 2 * lane) = H.u;
        *(uint32_t*)(ol + k * 64 + 2 * lane) = L.u;
    }
}

/* ------------------------- final epilogue — known good ------------------- */
__global__ __launch_bounds__(256) void k_epilogue(float* __restrict__ out)
{
    __shared__ float s2[COUT], h2[COUT], ss[COUT], hs[COUT];
    const int t = threadIdx.x;
    s2[t] = g_scale2[t];  h2[t] = g_shift2[t];
    ss[t] = g_scalesc[t]; hs[t] = g_shiftsc[t];
    __syncthreads();

    const int idx = blockIdx.x * 256 + t;          /* float4 index */
    const int c4 = (idx & 63) * 4;

    float4 x = ((float4*)out)[idx];
    float4 s = ((const float4*)g_sc)[idx];
    float v0 = x.x * s2[c4 + 0] + h2[c4 + 0]; v0 = v0 > 0.f ? v0 : SLOPE * v0;
    float v1 = x.y * s2[c4 + 1] + h2[c4 + 1]; v1 = v1 > 0.f ? v1 : SLOPE * v1;
    float v2 = x.z * s2[c4 + 2] + h2[c4 + 2]; v2 = v2 > 0.f ? v2 : SLOPE * v2;
    float v3 = x.w * s2[c4 + 3] + h2[c4 + 3]; v3 = v3 > 0.f ? v3 : SLOPE * v3;
    float4 r;
    r.x = v0 + s.x * ss[c4 + 0] + hs[c4 + 0];
    r.y = v1 + s.y * ss[c4 + 1] + hs[c4 + 1];
    r.z = v2 + s.z * ss[c4 + 2] + hs[c4 + 2];
    r.w = v3 + s.w * ss[c4 + 3] + hs[c4 + 3];
    ((float4*)out)[idx] = r;
}

/* ------------------------- launch ---------------------------------------- */
extern "C" void kernel_launch(void* const* d_in, const int* in_sizes, int n_in,
                              void* d_out, int out_size)
{
    const float* feats = (const float*)d_in[0];
    const float* xyz   = (const float*)d_in[1];
    const int*   nidx  = (const int*)d_in[3];
    const float* W1    = (const float*)d_in[4];
    const float* g1    = (const float*)d_in[5];
    const float* b1    = (const float*)d_in[6];
    const float* kp    = (const float*)d_in[7];
    const float* kpw   = (const float*)d_in[8];
    const float* W2    = (const float*)d_in[9];
    const float* g2    = (const float*)d_in[10];
    const float* b2    = (const float*)d_in[11];
    const float* Wsc   = (const float*)d_in[12];
    const float* gsc   = (const float*)d_in[13];
    const float* bsc   = (const float*)d_in[14];
    float* out = (float*)d_out;

    k_zero<<<1, 256>>>();
    k_prep_feats<<<(NPTS * CIN / 4) / 256, 256>>>(feats);
    k_prep_w<<<464, 256>>>(W1, Wsc, kpw, W2);

    /* unary1 */
    k_gemm_u1<<<dim3(NPTS / 128, 1), 256>>>();
    /* shortcut */
    k_gemm_sc<<<dim3(NPTS / 128, 4), 256>>>();

    k_stats1 <<<512, 256>>>();
    k_statssc<<<512, 256>>>();
    k_fin1 <<<1, D2>>>(g1, b1);
    k_finsc<<<1, COUT>>>(gsc, bsc);

    k_kpconv<<<NPTS / 8, 256>>>(xyz, nidx, kp);

    /* fk @ kpw -> xmid (bf16 split) */
    k_gemm_fk<<<dim3(NPTS / 128, 1), 256>>>();
    /* unary2 */
    k_gemm_u2<<<dim3(NPTS / 128, 4), 256>>>(out);

    k_stats2<<<512, 256>>>(out);
    k_fin2<<<1, COUT>>>(g2, b2);

    k_epilogue<<<(NPTS * (COUT / 4)) / 256, 256>>>(out);
}

// round 9
// speedup vs baseline: 1.3004x; 1.0417x over previous
#include <cuda_runtime.h>
#include <cuda_bf16.h>
#include <cstdint>

#define NPTS 80000
#define NBH  32
#define KPN  15
#define CIN  128
#define D2   64
#define COUT 256
#define FKDIM (KPN*D2)   /* 960 */
#define INV_INFL 2.5f
#define EPSBN 1e-5f
#define SLOPE 0.2f

typedef __nv_bfloat16 bf16;

/* ------------------------- device scratch ------------------------------- */
/* Referenced ONLY from device code (host-side &__device__ = ATS trap). */
__device__ float g_x1[(size_t)NPTS*D2];
__device__ float g_sc[(size_t)NPTS*COUT];
__device__ bf16  g_feats_hi[(size_t)NPTS*CIN], g_feats_lo[(size_t)NPTS*CIN];
__device__ bf16  g_fk_hi[(size_t)NPTS*FKDIM], g_fk_lo[(size_t)NPTS*FKDIM];
__device__ bf16  g_xmid_hi[(size_t)NPTS*D2],  g_xmid_lo[(size_t)NPTS*D2];

__device__ bf16 g_W1t_hi[D2*CIN],   g_W1t_lo[D2*CIN];
__device__ bf16 g_Wsct_hi[COUT*CIN],g_Wsct_lo[COUT*CIN];
__device__ bf16 g_kpwt_hi[D2*FKDIM],g_kpwt_lo[D2*FKDIM];
__device__ bf16 g_W2t_hi[COUT*D2],  g_W2t_lo[COUT*D2];

__device__ float g_sum1[D2],  g_sq1[D2],  g_scale1[D2],  g_shift1[D2];
__device__ float g_sumsc[COUT],g_sqsc[COUT],g_scalesc[COUT],g_shiftsc[COUT];
__device__ float g_sum2[COUT], g_sq2[COUT], g_scale2[COUT], g_shift2[COUT];

/* ------------------------- ptx helpers ---------------------------------- */
__device__ __forceinline__ void mma16816(float* c, const uint32_t* a, const uint32_t* b) {
    asm volatile("mma.sync.aligned.m16n8k16.row.col.f32.bf16.bf16.f32 "
        "{%0,%1,%2,%3}, {%4,%5,%6,%7}, {%8,%9}, {%0,%1,%2,%3};"
        : "+f"(c[0]), "+f"(c[1]), "+f"(c[2]), "+f"(c[3])
        : "r"(a[0]), "r"(a[1]), "r"(a[2]), "r"(a[3]), "r"(b[0]), "r"(b[1]));
}
__device__ __forceinline__ uint32_t ld32s(const bf16* p) {
    return *reinterpret_cast<const uint32_t*>(p);
}
__device__ __forceinline__ void cpasync16(void* s, const void* g) {
    uint32_t sa = (uint32_t)__cvta_generic_to_shared(s);
    asm volatile("cp.async.ca.shared.global [%0], [%1], 16;" :: "r"(sa), "l"(g) : "memory");
}
#define CP_COMMIT() asm volatile("cp.async.commit_group;" ::: "memory")
#define CP_WAIT1()  asm volatile("cp.async.wait_group 1;" ::: "memory")
#define CP_WAIT0()  asm volatile("cp.async.wait_group 0;" ::: "memory")

/* ------------------------- misc small kernels --------------------------- */
__global__ void k_zero() {
    int t = threadIdx.x;
    if (t < D2) { g_sum1[t] = 0.f; g_sq1[t] = 0.f; }
    g_sumsc[t] = 0.f; g_sqsc[t] = 0.f;
    g_sum2[t]  = 0.f; g_sq2[t]  = 0.f;
}

__device__ __forceinline__ void split_store(float v, bf16* hi, bf16* lo, size_t i) {
    bf16 h = __float2bfloat16(v);
    hi[i] = h;
    lo[i] = __float2bfloat16(v - __bfloat162float(h));
}

__global__ __launch_bounds__(256) void k_prep_feats(const float* __restrict__ f) {
    int i4 = blockIdx.x * 256 + threadIdx.x;            /* < 2,560,000 */
    float4 v = ((const float4*)f)[i4];
    bf16 h0 = __float2bfloat16(v.x), h1 = __float2bfloat16(v.y);
    bf16 h2 = __float2bfloat16(v.z), h3 = __float2bfloat16(v.w);
    union { bf16 b[4]; uint2 u; } H, L;
    H.b[0] = h0; H.b[1] = h1; H.b[2] = h2; H.b[3] = h3;
    L.b[0] = __float2bfloat16(v.x - __bfloat162float(h0));
    L.b[1] = __float2bfloat16(v.y - __bfloat162float(h1));
    L.b[2] = __float2bfloat16(v.z - __bfloat162float(h2));
    L.b[3] = __float2bfloat16(v.w - __bfloat162float(h3));
    ((uint2*)g_feats_hi)[i4] = H.u;
    ((uint2*)g_feats_lo)[i4] = L.u;
}

__global__ __launch_bounds__(256) void k_prep_w(const float* __restrict__ W1,
                                                const float* __restrict__ Wsc,
                                                const float* __restrict__ kpw,
                                                const float* __restrict__ W2)
{
    int i = blockIdx.x * 256 + threadIdx.x;             /* < 118784 */
    if (i < 8192) {                                     /* W1t [64,128] */
        int e = i >> 7, k = i & 127;
        split_store(W1[k * D2 + e], g_W1t_hi, g_W1t_lo, i);
    } else if (i < 40960) {                             /* Wsct [256,128] */
        int j = i - 8192; int e = j >> 7, k = j & 127;
        split_store(Wsc[k * COUT + e], g_Wsct_hi, g_Wsct_lo, j);
    } else if (i < 102400) {                            /* kpwt [64,960] */
        int j = i - 40960; int e = j / FKDIM, kd = j % FKDIM;
        split_store(kpw[(size_t)kd * D2 + e], g_kpwt_hi, g_kpwt_lo, j);
    } else {                                            /* W2t [256,64] */
        int j = i - 102400; int e = j >> 6, k = j & 63;
        split_store(W2[k * COUT + e], g_W2t_hi, g_W2t_lo, j);
    }
}

/* ---------------- channel stats — known good ---------------------------- */
template <int C>
__device__ __forceinline__ void stats_body(const float* __restrict__ X,
                                           float* sum, float* sq)
{
    constexpr int REPS = 256 / C;
    const int t = threadIdx.x;
    const int c = t % C;
    const int rep = t / C;
    float s = 0.f, s2 = 0.f;
    for (int r = blockIdx.x * REPS + rep; r < NPTS; r += gridDim.x * REPS) {
        float v = X[(size_t)r * C + c];
        s += v; s2 += v * v;
    }
    atomicAdd(&sum[c], s);
    atomicAdd(&sq[c], s2);
}
__global__ void k_stats1()               { stats_body<D2>(g_x1, g_sum1, g_sq1); }
__global__ void k_statssc()              { stats_body<COUT>(g_sc, g_sumsc, g_sqsc); }
__global__ void k_stats2(const float* X) { stats_body<COUT>(X, g_sum2, g_sq2); }

__device__ __forceinline__ void fin_body(const float* sum, const float* sq,
                                         const float* g, const float* b,
                                         float* scale, float* shift)
{
    int c = threadIdx.x;
    float m = sum[c] * (1.0f / NPTS);
    float v = sq[c] * (1.0f / NPTS) - m * m;
    float s = g[c] * rsqrtf(v + EPSBN);
    scale[c] = s;
    shift[c] = b[c] - m * s;
}
__global__ void k_fin1(const float* g, const float* b)  { fin_body(g_sum1, g_sq1, g, b, g_scale1, g_shift1); }
__global__ void k_finsc(const float* g, const float* b) { fin_body(g_sumsc, g_sqsc, g, b, g_scalesc, g_shiftsc); }
__global__ void k_fin2(const float* g, const float* b)  { fin_body(g_sum2, g_sq2, g, b, g_scale2, g_shift2); }

/* ------------------------- HMMA split-bf16 GEMM + cp.async pipeline ------ */
/* Tile 128x64, 256 thr = 8 warps (4 m x 2 n), warp tile 32x32.
   VERIFIED fragment addressing (R7/R8); the only new mechanism vs R8 is
   double-buffered cp.async staging.
   Dynamic smem: 2 buffers x (Ah[128*40] Al[128*40] Bh[64*40] Bl[64*40])
   = 2 x 15360 elems = 61440 B. */
#define AST 40
#define BUF_ELEMS 15360
#define OFF_AL 5120
#define OFF_BH 10240
#define OFF_BL 12800
#define GEMM_SMEM 61440

template<int KTOT, int MODE>
__device__ __forceinline__ void mmagemm_body(
    const bf16* __restrict__ Ahi, const bf16* __restrict__ Alo,
    const bf16* __restrict__ Bhi, const bf16* __restrict__ Blo,
    float* __restrict__ Cf, int ldc,
    bf16* __restrict__ Chi, bf16* __restrict__ Clo)
{
    extern __shared__ __align__(16) bf16 smem[];

    const int t = threadIdx.x, lane = t & 31, wid = t >> 5;
    const int wm = wid & 3, wn = wid >> 2;
    const int m0 = blockIdx.x * 128, n0 = blockIdx.y * 64;
    const int gr = lane >> 2, gc2 = (lane & 3) * 2;

    /* staging coords (same data layout as R8) */
    const int arow0 = t >> 2, ac8 = (t & 3) * 8;        /* A: rows 0-63 (+64) */
    const int brow = t >> 2,  bc8 = (t & 3) * 8;        /* B: rows 0-63 */

    float acc[2][4][4];
#pragma unroll
    for (int i = 0; i < 2; i++)
#pragma unroll
        for (int j = 0; j < 4; j++)
#pragma unroll
            for (int q = 0; q < 4; q++) acc[i][j][q] = 0.f;

    constexpr int NCH = KTOT / 32;

    auto issue = [&](int kc) {
        bf16* buf = smem + (kc & 1) * BUF_ELEMS;
        /* A: 128 rows x 32 elems, 2 x 16B per plane per thread */
#pragma unroll
        for (int it = 0; it < 2; it++) {
            int row = arow0 + it * 64;
            size_t gsrc = (size_t)(m0 + row) * KTOT + kc * 32 + ac8;
            cpasync16(buf + row * AST + ac8, Ahi + gsrc);
            cpasync16(buf + OFF_AL + row * AST + ac8, Alo + gsrc);
        }
        /* B: 64 rows x 32 elems, 1 x 16B per plane per thread */
        {
            size_t gsrc = (size_t)(n0 + brow) * KTOT + kc * 32 + bc8;
            cpasync16(buf + OFF_BH + brow * AST + bc8, Bhi + gsrc);
            cpasync16(buf + OFF_BL + brow * AST + bc8, Blo + gsrc);
        }
        CP_COMMIT();
    };

    issue(0);

    for (int kc = 0; kc < NCH; kc++) {
        if (kc + 1 < NCH) { issue(kc + 1); CP_WAIT1(); }
        else              { CP_WAIT0(); }
        __syncthreads();

        const bf16* sAh = smem + (kc & 1) * BUF_ELEMS;
        const bf16* sAl = sAh + OFF_AL;
        const bf16* sBh = sAh + OFF_BH;
        const bf16* sBl = sAh + OFF_BL;

#pragma unroll
        for (int kk = 0; kk < 2; kk++) {
            const int kb = kk * 16;
            uint32_t ah[2][4], al[2][4], bh[4][2], bl[4][2];
#pragma unroll
            for (int mt = 0; mt < 2; mt++) {
                const bf16* ph = sAh + (wm * 32 + mt * 16 + gr) * AST + kb + gc2;
                ah[mt][0] = ld32s(ph);
                ah[mt][1] = ld32s(ph + 8 * AST);
                ah[mt][2] = ld32s(ph + 8);
                ah[mt][3] = ld32s(ph + 8 * AST + 8);
                const bf16* pl = sAl + (wm * 32 + mt * 16 + gr) * AST + kb + gc2;
                al[mt][0] = ld32s(pl);
                al[mt][1] = ld32s(pl + 8 * AST);
                al[mt][2] = ld32s(pl + 8);
                al[mt][3] = ld32s(pl + 8 * AST + 8);
            }
#pragma unroll
            for (int nt = 0; nt < 4; nt++) {
                const bf16* ph = sBh + (wn * 32 + nt * 8 + gr) * AST + kb + gc2;
                bh[nt][0] = ld32s(ph);
                bh[nt][1] = ld32s(ph + 8);
                const bf16* pl = sBl + (wn * 32 + nt * 8 + gr) * AST + kb + gc2;
                bl[nt][0] = ld32s(pl);
                bl[nt][1] = ld32s(pl + 8);
            }
#pragma unroll
            for (int mt = 0; mt < 2; mt++)
#pragma unroll
                for (int nt = 0; nt < 4; nt++) {
                    mma16816(acc[mt][nt], ah[mt], bh[nt]);
                    mma16816(acc[mt][nt], ah[mt], bl[nt]);
                    mma16816(acc[mt][nt], al[mt], bh[nt]);
                }
        }
        __syncthreads();   /* buffer kc&1 free for issue(kc+2) */
    }

    const int rbase = m0 + wm * 32 + gr;
    const int cbase = wn * 32 + gc2;

    if (MODE == 0) {
#pragma unroll
        for (int mt = 0; mt < 2; mt++)
#pragma unroll
            for (int nt = 0; nt < 4; nt++) {
                int r0 = rbase + mt * 16, r1 = r0 + 8;
                int cc = n0 + cbase + nt * 8;
                *(float2*)(Cf + (size_t)r0 * ldc + cc) =
                    make_float2(acc[mt][nt][0], acc[mt][nt][1]);
                *(float2*)(Cf + (size_t)r1 * ldc + cc) =
                    make_float2(acc[mt][nt][2], acc[mt][nt][3]);
            }
    } else {
#pragma unroll
        for (int mt = 0; mt < 2; mt++)
#pragma unroll
            for (int nt = 0; nt < 4; nt++) {
                int cc = n0 + cbase + nt * 8;
#pragma unroll
                for (int half = 0; half < 2; half++) {
                    int rr = rbase + mt * 16 + half * 8;
                    float v0 = acc[mt][nt][half * 2 + 0];
                    float v1 = acc[mt][nt][half * 2 + 1];
                    union { bf16 b[2]; uint32_t u; } H, L;
                    bf16 h0 = __float2bfloat16(v0), h1 = __float2bfloat16(v1);
                    H.b[0] = h0; H.b[1] = h1;
                    L.b[0] = __float2bfloat16(v0 - __bfloat162float(h0));
                    L.b[1] = __float2bfloat16(v1 - __bfloat162float(h1));
                    *(uint32_t*)(Chi + (size_t)rr * 64 + cc) = H.u;
                    *(uint32_t*)(Clo + (size_t)rr * 64 + cc) = L.u;
                }
            }
    }
}

/* wrappers: globals bound in DEVICE code */
__global__ __launch_bounds__(256) void k_gemm_u1() {
    mmagemm_body<128, 0>(g_feats_hi, g_feats_lo, g_W1t_hi, g_W1t_lo,
                         g_x1, D2, nullptr, nullptr);
}
__global__ __launch_bounds__(256) void k_gemm_sc() {
    mmagemm_body<128, 0>(g_feats_hi, g_feats_lo, g_Wsct_hi, g_Wsct_lo,
                         g_sc, COUT, nullptr, nullptr);
}
__global__ __launch_bounds__(256) void k_gemm_fk() {
    mmagemm_body<960, 1>(g_fk_hi, g_fk_lo, g_kpwt_hi, g_kpwt_lo,
                         nullptr, 0, g_xmid_hi, g_xmid_lo);
}
__global__ __launch_bounds__(256) void k_gemm_u2(float* __restrict__ out) {
    mmagemm_body<64, 0>(g_xmid_hi, g_xmid_lo, g_W2t_hi, g_W2t_lo,
                        out, COUT, nullptr, nullptr);
}

/* ------------------------- KPConv (sparse influence) -------------------- */
__device__ __forceinline__ float fsqrt_approx(float x) {
    float r; asm("sqrt.approx.f32 %0, %1;" : "=f"(r) : "f"(x)); return r;
}

__global__ __launch_bounds__(256) void k_kpconv(const float* __restrict__ xyz,
                                                const int* __restrict__ nidx,
                                                const float* __restrict__ kp)
{
    __shared__ float kps[KPN][3];
    __shared__ float ws[8][NBH][KPN];
    const int t = threadIdx.x;
    if (t < KPN * 3) ((float*)kps)[t] = kp[t];
    __syncthreads();

    const int warp = t >> 5, lane = t & 31;
    const int n = blockIdx.x * 8 + warp;

    const float cx = xyz[n * 3 + 0], cy = xyz[n * 3 + 1], cz = xyz[n * 3 + 2];
    const int j = nidx[n * NBH + lane];
    const float rx = xyz[j * 3 + 0] - cx;
    const float ry = xyz[j * 3 + 1] - cy;
    const float rz = xyz[j * 3 + 2] - cz;

    unsigned mask = 0;
#pragma unroll
    for (int k = 0; k < KPN; k++) {
        float dx = rx - kps[k][0], dy = ry - kps[k][1], dz = rz - kps[k][2];
        float sq = dx * dx + dy * dy + dz * dz;
        float w = 1.0f - fsqrt_approx(sq) * INV_INFL;
        w = w > 0.f ? w : 0.f;
        ws[warp][lane][k] = w;
        if (w > 0.f) mask |= (1u << k);
    }
    __syncwarp();

    const float sc0 = g_scale1[2 * lane], sc1 = g_scale1[2 * lane + 1];
    const float sh0 = g_shift1[2 * lane], sh1 = g_shift1[2 * lane + 1];
    const float2* x1v = (const float2*)g_x1;

    float fk0[KPN], fk1[KPN];
#pragma unroll
    for (int k = 0; k < KPN; k++) { fk0[k] = 0.f; fk1[k] = 0.f; }

    for (int h = 0; h < NBH; h++) {
        unsigned mh = __shfl_sync(0xffffffffu, mask, h);
        if (!mh) continue;                                 /* warp-uniform */
        int jj = __shfl_sync(0xffffffffu, j, h);
        float2 v = x1v[(size_t)jj * 32 + lane];
        float a = v.x * sc0 + sh0; a = a > 0.f ? a : SLOPE * a;
        float b = v.y * sc1 + sh1; b = b > 0.f ? b : SLOPE * b;
        while (mh) {
            int k = __ffs(mh) - 1; mh &= mh - 1;
            float w = ws[warp][h][k];
            fk0[k] += w * a;
            fk1[k] += w * b;
        }
    }

    bf16* oh = g_fk_hi + (size_t)n * FKDIM;
    bf16* ol = g_fk_lo + (size_t)n * FKDIM;
#pragma unroll
    for (int k = 0; k < KPN; k++) {
        union { bf16 b[2]; uint32_t u; } H, L;
        bf16 h0 = __float2bfloat16(fk0[k]), h1 = __float2bfloat16(fk1[k]);
        H.b[0] = h0; H.b[1] = h1;
        L.b[0] = __float2bfloat16(fk0[k] - __bfloat162float(h0));
        L.b[1] = __float2bfloat16(fk1[k] - __bfloat162float(h1));
        *(uint32_t*)(oh + k * 64 + 2 * lane) = H.u;
        *(uint32_t*)(ol + k * 64 + 2 * lane) = L.u;
    }
}

/* ------------------------- final epilogue — known good ------------------- */
__global__ __launch_bounds__(256) void k_epilogue(float* __restrict__ out)
{
    __shared__ float s2[COUT], h2[COUT], ss[COUT], hs[COUT];
    const int t = threadIdx.x;
    s2[t] = g_scale2[t];  h2[t] = g_shift2[t];
    ss[t] = g_scalesc[t]; hs[t] = g_shiftsc[t];
    __syncthreads();

    const int idx = blockIdx.x * 256 + t;          /* float4 index */
    const int c4 = (idx & 63) * 4;

    float4 x = ((float4*)out)[idx];
    float4 s = ((const float4*)g_sc)[idx];
    float v0 = x.x * s2[c4 + 0] + h2[c4 + 0]; v0 = v0 > 0.f ? v0 : SLOPE * v0;
    float v1 = x.y * s2[c4 + 1] + h2[c4 + 1]; v1 = v1 > 0.f ? v1 : SLOPE * v1;
    float v2 = x.z * s2[c4 + 2] + h2[c4 + 2]; v2 = v2 > 0.f ? v2 : SLOPE * v2;
    float v3 = x.w * s2[c4 + 3] + h2[c4 + 3]; v3 = v3 > 0.f ? v3 : SLOPE * v3;
    float4 r;
    r.x = v0 + s.x * ss[c4 + 0] + hs[c4 + 0];
    r.y = v1 + s.y * ss[c4 + 1] + hs[c4 + 1];
    r.z = v2 + s.z * ss[c4 + 2] + hs[c4 + 2];
    r.w = v3 + s.w * ss[c4 + 3] + hs[c4 + 3];
    ((float4*)out)[idx] = r;
}

/* ------------------------- launch ---------------------------------------- */
extern "C" void kernel_launch(void* const* d_in, const int* in_sizes, int n_in,
                              void* d_out, int out_size)
{
    const float* feats = (const float*)d_in[0];
    const float* xyz   = (const float*)d_in[1];
    const int*   nidx  = (const int*)d_in[3];
    const float* W1    = (const float*)d_in[4];
    const float* g1    = (const float*)d_in[5];
    const float* b1    = (const float*)d_in[6];
    const float* kp    = (const float*)d_in[7];
    const float* kpw   = (const float*)d_in[8];
    const float* W2    = (const float*)d_in[9];
    const float* g2    = (const float*)d_in[10];
    const float* b2    = (const float*)d_in[11];
    const float* Wsc   = (const float*)d_in[12];
    const float* gsc   = (const float*)d_in[13];
    const float* bsc   = (const float*)d_in[14];
    float* out = (float*)d_out;

    static bool attr_done = false;
    if (!attr_done) {
        cudaFuncSetAttribute(k_gemm_u1, cudaFuncAttributeMaxDynamicSharedMemorySize, GEMM_SMEM);
        cudaFuncSetAttribute(k_gemm_sc, cudaFuncAttributeMaxDynamicSharedMemorySize, GEMM_SMEM);
        cudaFuncSetAttribute(k_gemm_fk, cudaFuncAttributeMaxDynamicSharedMemorySize, GEMM_SMEM);
        cudaFuncSetAttribute(k_gemm_u2, cudaFuncAttributeMaxDynamicSharedMemorySize, GEMM_SMEM);
        attr_done = true;
    }

    k_zero<<<1, 256>>>();
    k_prep_feats<<<(NPTS * CIN / 4) / 256, 256>>>(feats);
    k_prep_w<<<464, 256>>>(W1, Wsc, kpw, W2);

    /* unary1 */
    k_gemm_u1<<<dim3(NPTS / 128, 1), 256, GEMM_SMEM>>>();
    /* shortcut */
    k_gemm_sc<<<dim3(NPTS / 128, 4), 256, GEMM_SMEM>>>();

    k_stats1 <<<512, 256>>>();
    k_statssc<<<512, 256>>>();
    k_fin1 <<<1, D2>>>(g1, b1);
    k_finsc<<<1, COUT>>>(gsc, bsc);

    k_kpconv<<<NPTS / 8, 256>>>(xyz, nidx, kp);

    /* fk @ kpw -> xmid (bf16 split) */
    k_gemm_fk<<<dim3(NPTS / 128, 1), 256, GEMM_SMEM>>>();
    /* unary2 */
    k_gemm_u2<<<dim3(NPTS / 128, 4), 256, GEMM_SMEM>>>(out);

    k_stats2<<<512, 256>>>(out);
    k_fin2<<<1, COUT>>>(g2, b2);

    k_epilogue<<<(NPTS * (COUT / 4)) / 256, 256>>>(out);
}

// round 10
// speedup vs baseline: 1.6202x; 1.2460x over previous
#include <cuda_runtime.h>
#include <cuda_bf16.h>
#include <cstdint>

#define NPTS 80000
#define NBH  32
#define KPN  15
#define CIN  128
#define D2   64
#define COUT 256
#define FKDIM (KPN*D2)   /* 960 */
#define INV_INFL 2.5f
#define EPSBN 1e-5f
#define SLOPE 0.2f

typedef __nv_bfloat16 bf16;

/* ------------------------- device scratch ------------------------------- */
/* Referenced ONLY from device code (host-side &__device__ = ATS trap). */
__device__ float g_x1[(size_t)NPTS*D2];
__device__ float g_sc[(size_t)NPTS*COUT];
__device__ bf16  g_feats_hi[(size_t)NPTS*CIN], g_feats_lo[(size_t)NPTS*CIN];
__device__ bf16  g_fk_hi[(size_t)NPTS*FKDIM], g_fk_lo[(size_t)NPTS*FKDIM];
__device__ bf16  g_xmid_hi[(size_t)NPTS*D2],  g_xmid_lo[(size_t)NPTS*D2];

__device__ bf16 g_W1t_hi[D2*CIN],   g_W1t_lo[D2*CIN];
__device__ bf16 g_Wsct_hi[COUT*CIN],g_Wsct_lo[COUT*CIN];
__device__ bf16 g_kpwt_hi[D2*FKDIM],g_kpwt_lo[D2*FKDIM];
__device__ bf16 g_W2t_hi[COUT*D2],  g_W2t_lo[COUT*D2];

__device__ float g_sum1[D2],  g_sq1[D2],  g_scale1[D2],  g_shift1[D2];
__device__ float g_sumsc[COUT],g_sqsc[COUT],g_scalesc[COUT],g_shiftsc[COUT];
__device__ float g_sum2[COUT], g_sq2[COUT], g_scale2[COUT], g_shift2[COUT];

/* ------------------------- ptx helpers ---------------------------------- */
__device__ __forceinline__ void mma16816(float* c, const uint32_t* a, const uint32_t* b) {
    asm volatile("mma.sync.aligned.m16n8k16.row.col.f32.bf16.bf16.f32 "
        "{%0,%1,%2,%3}, {%4,%5,%6,%7}, {%8,%9}, {%0,%1,%2,%3};"
        : "+f"(c[0]), "+f"(c[1]), "+f"(c[2]), "+f"(c[3])
        : "r"(a[0]), "r"(a[1]), "r"(a[2]), "r"(a[3]), "r"(b[0]), "r"(b[1]));
}
__device__ __forceinline__ uint32_t ld32s(const bf16* p) {
    return *reinterpret_cast<const uint32_t*>(p);
}
__device__ __forceinline__ void cpasync16(void* s, const void* g) {
    uint32_t sa = (uint32_t)__cvta_generic_to_shared(s);
    asm volatile("cp.async.ca.shared.global [%0], [%1], 16;" :: "r"(sa), "l"(g) : "memory");
}
#define CP_COMMIT() asm volatile("cp.async.commit_group;" ::: "memory")
#define CP_WAIT1()  asm volatile("cp.async.wait_group 1;" ::: "memory")
#define CP_WAIT0()  asm volatile("cp.async.wait_group 0;" ::: "memory")

/* ------------------------- misc small kernels --------------------------- */
__global__ void k_zero() {
    int t = threadIdx.x;
    if (t < D2) { g_sum1[t] = 0.f; g_sq1[t] = 0.f; }
    g_sumsc[t] = 0.f; g_sqsc[t] = 0.f;
    g_sum2[t]  = 0.f; g_sq2[t]  = 0.f;
}

__device__ __forceinline__ void split_store(float v, bf16* hi, bf16* lo, size_t i) {
    bf16 h = __float2bfloat16(v);
    hi[i] = h;
    lo[i] = __float2bfloat16(v - __bfloat162float(h));
}

__global__ __launch_bounds__(256) void k_prep_feats(const float* __restrict__ f) {
    int i4 = blockIdx.x * 256 + threadIdx.x;            /* < 2,560,000 */
    float4 v = ((const float4*)f)[i4];
    bf16 h0 = __float2bfloat16(v.x), h1 = __float2bfloat16(v.y);
    bf16 h2 = __float2bfloat16(v.z), h3 = __float2bfloat16(v.w);
    union { bf16 b[4]; uint2 u; } H, L;
    H.b[0] = h0; H.b[1] = h1; H.b[2] = h2; H.b[3] = h3;
    L.b[0] = __float2bfloat16(v.x - __bfloat162float(h0));
    L.b[1] = __float2bfloat16(v.y - __bfloat162float(h1));
    L.b[2] = __float2bfloat16(v.z - __bfloat162float(h2));
    L.b[3] = __float2bfloat16(v.w - __bfloat162float(h3));
    ((uint2*)g_feats_hi)[i4] = H.u;
    ((uint2*)g_feats_lo)[i4] = L.u;
}

__global__ __launch_bounds__(256) void k_prep_w(const float* __restrict__ W1,
                                                const float* __restrict__ Wsc,
                                                const float* __restrict__ kpw,
                                                const float* __restrict__ W2)
{
    int i = blockIdx.x * 256 + threadIdx.x;             /* < 118784 */
    if (i < 8192) {                                     /* W1t [64,128] */
        int e = i >> 7, k = i & 127;
        split_store(W1[k * D2 + e], g_W1t_hi, g_W1t_lo, i);
    } else if (i < 40960) {                             /* Wsct [256,128] */
        int j = i - 8192; int e = j >> 7, k = j & 127;
        split_store(Wsc[k * COUT + e], g_Wsct_hi, g_Wsct_lo, j);
    } else if (i < 102400) {                            /* kpwt [64,960] */
        int j = i - 40960; int e = j / FKDIM, kd = j % FKDIM;
        split_store(kpw[(size_t)kd * D2 + e], g_kpwt_hi, g_kpwt_lo, j);
    } else {                                            /* W2t [256,64] */
        int j = i - 102400; int e = j >> 6, k = j & 63;
        split_store(W2[k * COUT + e], g_W2t_hi, g_W2t_lo, j);
    }
}

__device__ __forceinline__ void fin_body(const float* sum, const float* sq,
                                         const float* g, const float* b,
                                         float* scale, float* shift)
{
    int c = threadIdx.x;
    float m = sum[c] * (1.0f / NPTS);
    float v = sq[c] * (1.0f / NPTS) - m * m;
    float s = g[c] * rsqrtf(v + EPSBN);
    scale[c] = s;
    shift[c] = b[c] - m * s;
}
__global__ void k_fin1(const float* g, const float* b)  { fin_body(g_sum1, g_sq1, g, b, g_scale1, g_shift1); }
__global__ void k_finsc(const float* g, const float* b) { fin_body(g_sumsc, g_sqsc, g, b, g_scalesc, g_shiftsc); }
__global__ void k_fin2(const float* g, const float* b)  { fin_body(g_sum2, g_sq2, g, b, g_scale2, g_shift2); }

/* ------------------------- HMMA split-bf16 GEMM + cp.async pipeline ------ */
/* Tile 128x64, 256 thr = 8 warps (4 m x 2 n), warp tile 32x32.
   VERIFIED fragment addressing + double-buffered cp.async (R9).
   NEW in R10: MODE 0 fuses BN stats (per-column sum/sumsq) into the
   epilogue — butterfly reduce over gr lanes, smem accumulate, one global
   atomicAdd per column per CTA.
   D = Ah*Bh + Ah*Bl + Al*Bh (fp32 accum).
   MODE 0: fp32 C + stats.  MODE 1: split bf16 hi/lo C (ld 64). */
#define AST 40
#define BUF_ELEMS 15360
#define OFF_AL 5120
#define OFF_BH 10240
#define OFF_BL 12800
#define GEMM_SMEM 61440

template<int KTOT, int MODE>
__device__ __forceinline__ void mmagemm_body(
    const bf16* __restrict__ Ahi, const bf16* __restrict__ Alo,
    const bf16* __restrict__ Bhi, const bf16* __restrict__ Blo,
    float* __restrict__ Cf, int ldc,
    bf16* __restrict__ Chi, bf16* __restrict__ Clo,
    float* __restrict__ sumP, float* __restrict__ sqP)
{
    extern __shared__ __align__(16) bf16 smem[];

    const int t = threadIdx.x, lane = t & 31, wid = t >> 5;
    const int wm = wid & 3, wn = wid >> 2;
    const int m0 = blockIdx.x * 128, n0 = blockIdx.y * 64;
    const int gr = lane >> 2, gc2 = (lane & 3) * 2;

    const int arow0 = t >> 2, ac8 = (t & 3) * 8;
    const int brow = t >> 2,  bc8 = (t & 3) * 8;

    float acc[2][4][4];
#pragma unroll
    for (int i = 0; i < 2; i++)
#pragma unroll
        for (int j = 0; j < 4; j++)
#pragma unroll
            for (int q = 0; q < 4; q++) acc[i][j][q] = 0.f;

    constexpr int NCH = KTOT / 32;

    auto issue = [&](int kc) {
        bf16* buf = smem + (kc & 1) * BUF_ELEMS;
#pragma unroll
        for (int it = 0; it < 2; it++) {
            int row = arow0 + it * 64;
            size_t gsrc = (size_t)(m0 + row) * KTOT + kc * 32 + ac8;
            cpasync16(buf + row * AST + ac8, Ahi + gsrc);
            cpasync16(buf + OFF_AL + row * AST + ac8, Alo + gsrc);
        }
        {
            size_t gsrc = (size_t)(n0 + brow) * KTOT + kc * 32 + bc8;
            cpasync16(buf + OFF_BH + brow * AST + bc8, Bhi + gsrc);
            cpasync16(buf + OFF_BL + brow * AST + bc8, Blo + gsrc);
        }
        CP_COMMIT();
    };

    issue(0);

    for (int kc = 0; kc < NCH; kc++) {
        if (kc + 1 < NCH) { issue(kc + 1); CP_WAIT1(); }
        else              { CP_WAIT0(); }
        __syncthreads();

        const bf16* sAh = smem + (kc & 1) * BUF_ELEMS;
        const bf16* sAl = sAh + OFF_AL;
        const bf16* sBh = sAh + OFF_BH;
        const bf16* sBl = sAh + OFF_BL;

#pragma unroll
        for (int kk = 0; kk < 2; kk++) {
            const int kb = kk * 16;
            uint32_t ah[2][4], al[2][4], bh[4][2], bl[4][2];
#pragma unroll
            for (int mt = 0; mt < 2; mt++) {
                const bf16* ph = sAh + (wm * 32 + mt * 16 + gr) * AST + kb + gc2;
                ah[mt][0] = ld32s(ph);
                ah[mt][1] = ld32s(ph + 8 * AST);
                ah[mt][2] = ld32s(ph + 8);
                ah[mt][3] = ld32s(ph + 8 * AST + 8);
                const bf16* pl = sAl + (wm * 32 + mt * 16 + gr) * AST + kb + gc2;
                al[mt][0] = ld32s(pl);
                al[mt][1] = ld32s(pl + 8 * AST);
                al[mt][2] = ld32s(pl + 8);
                al[mt][3] = ld32s(pl + 8 * AST + 8);
            }
#pragma unroll
            for (int nt = 0; nt < 4; nt++) {
                const bf16* ph = sBh + (wn * 32 + nt * 8 + gr) * AST + kb + gc2;
                bh[nt][0] = ld32s(ph);
                bh[nt][1] = ld32s(ph + 8);
                const bf16* pl = sBl + (wn * 32 + nt * 8 + gr) * AST + kb + gc2;
                bl[nt][0] = ld32s(pl);
                bl[nt][1] = ld32s(pl + 8);
            }
#pragma unroll
            for (int mt = 0; mt < 2; mt++)
#pragma unroll
                for (int nt = 0; nt < 4; nt++) {
                    mma16816(acc[mt][nt], ah[mt], bh[nt]);
                    mma16816(acc[mt][nt], ah[mt], bl[nt]);
                    mma16816(acc[mt][nt], al[mt], bh[nt]);
                }
        }
        __syncthreads();
    }

    const int rbase = m0 + wm * 32 + gr;
    const int cbase = wn * 32 + gc2;

    if (MODE == 0) {
        /* C stores */
#pragma unroll
        for (int mt = 0; mt < 2; mt++)
#pragma unroll
            for (int nt = 0; nt < 4; nt++) {
                int r0 = rbase + mt * 16, r1 = r0 + 8;
                int cc = n0 + cbase + nt * 8;
                *(float2*)(Cf + (size_t)r0 * ldc + cc) =
                    make_float2(acc[mt][nt][0], acc[mt][nt][1]);
                *(float2*)(Cf + (size_t)r1 * ldc + cc) =
                    make_float2(acc[mt][nt][2], acc[mt][nt][3]);
            }

        /* fused BN stats: per-thread 8 columns x 4 rows */
        float cs[8], cq[8];
#pragma unroll
        for (int nt = 0; nt < 4; nt++)
#pragma unroll
            for (int j = 0; j < 2; j++) {
                float v0 = acc[0][nt][j],     v1 = acc[0][nt][2 + j];
                float v2 = acc[1][nt][j],     v3 = acc[1][nt][2 + j];
                cs[nt * 2 + j] = v0 + v1 + v2 + v3;
                cq[nt * 2 + j] = v0 * v0 + v1 * v1 + v2 * v2 + v3 * v3;
            }
        /* butterfly over gr lanes (lane bits 2,3,4) */
#pragma unroll
        for (int off = 4; off < 32; off <<= 1)
#pragma unroll
            for (int i = 0; i < 8; i++) {
                cs[i] += __shfl_xor_sync(0xffffffffu, cs[i], off);
                cq[i] += __shfl_xor_sync(0xffffffffu, cq[i], off);
            }

        float* fs = (float*)smem;          /* [0:64) sum, [64:128) sq */
        if (t < 128) fs[t] = 0.f;
        __syncthreads();
        if ((lane & 28) == 0) {            /* gr == 0, i.e. lane < 4 */
#pragma unroll
            for (int nt = 0; nt < 4; nt++)
#pragma unroll
                for (int j = 0; j < 2; j++) {
                    int col = wn * 32 + (lane & 3) * 2 + nt * 8 + j;
                    atomicAdd(&fs[col],      cs[nt * 2 + j]);
                    atomicAdd(&fs[64 + col], cq[nt * 2 + j]);
                }
        }
        __syncthreads();
        if (t < 64) {
            atomicAdd(&sumP[n0 + t], fs[t]);
            atomicAdd(&sqP[n0 + t],  fs[64 + t]);
        }
    } else {
#pragma unroll
        for (int mt = 0; mt < 2; mt++)
#pragma unroll
            for (int nt = 0; nt < 4; nt++) {
                int cc = n0 + cbase + nt * 8;
#pragma unroll
                for (int half = 0; half < 2; half++) {
                    int rr = rbase + mt * 16 + half * 8;
                    float v0 = acc[mt][nt][half * 2 + 0];
                    float v1 = acc[mt][nt][half * 2 + 1];
                    union { bf16 b[2]; uint32_t u; } H, L;
                    bf16 h0 = __float2bfloat16(v0), h1 = __float2bfloat16(v1);
                    H.b[0] = h0; H.b[1] = h1;
                    L.b[0] = __float2bfloat16(v0 - __bfloat162float(h0));
                    L.b[1] = __float2bfloat16(v1 - __bfloat162float(h1));
                    *(uint32_t*)(Chi + (size_t)rr * 64 + cc) = H.u;
                    *(uint32_t*)(Clo + (size_t)rr * 64 + cc) = L.u;
                }
            }
    }
}

/* wrappers: globals bound in DEVICE code */
__global__ __launch_bounds__(256) void k_gemm_u1() {
    mmagemm_body<128, 0>(g_feats_hi, g_feats_lo, g_W1t_hi, g_W1t_lo,
                         g_x1, D2, nullptr, nullptr, g_sum1, g_sq1);
}
__global__ __launch_bounds__(256) void k_gemm_sc() {
    mmagemm_body<128, 0>(g_feats_hi, g_feats_lo, g_Wsct_hi, g_Wsct_lo,
                         g_sc, COUT, nullptr, nullptr, g_sumsc, g_sqsc);
}
__global__ __launch_bounds__(256) void k_gemm_fk() {
    mmagemm_body<960, 1>(g_fk_hi, g_fk_lo, g_kpwt_hi, g_kpwt_lo,
                         nullptr, 0, g_xmid_hi, g_xmid_lo, nullptr, nullptr);
}
__global__ __launch_bounds__(256) void k_gemm_u2(float* __restrict__ out) {
    mmagemm_body<64, 0>(g_xmid_hi, g_xmid_lo, g_W2t_hi, g_W2t_lo,
                        out, COUT, nullptr, nullptr, g_sum2, g_sq2);
}

/* ------------------------- KPConv (sparse influence) -------------------- */
__device__ __forceinline__ float fsqrt_approx(float x) {
    float r; asm("sqrt.approx.f32 %0, %1;" : "=f"(r) : "f"(x)); return r;
}

__global__ __launch_bounds__(256) void k_kpconv(const float* __restrict__ xyz,
                                                const int* __restrict__ nidx,
                                                const float* __restrict__ kp)
{
    __shared__ float kps[KPN][3];
    __shared__ float ws[8][NBH][KPN];
    const int t = threadIdx.x;
    if (t < KPN * 3) ((float*)kps)[t] = kp[t];
    __syncthreads();

    const int warp = t >> 5, lane = t & 31;
    const int n = blockIdx.x * 8 + warp;

    const float cx = xyz[n * 3 + 0], cy = xyz[n * 3 + 1], cz = xyz[n * 3 + 2];
    const int j = nidx[n * NBH + lane];
    const float rx = xyz[j * 3 + 0] - cx;
    const float ry = xyz[j * 3 + 1] - cy;
    const float rz = xyz[j * 3 + 2] - cz;

    unsigned mask = 0;
#pragma unroll
    for (int k = 0; k < KPN; k++) {
        float dx = rx - kps[k][0], dy = ry - kps[k][1], dz = rz - kps[k][2];
        float sq = dx * dx + dy * dy + dz * dz;
        float w = 1.0f - fsqrt_approx(sq) * INV_INFL;
        w = w > 0.f ? w : 0.f;
        ws[warp][lane][k] = w;
        if (w > 0.f) mask |= (1u << k);
    }
    __syncwarp();

    const float sc0 = g_scale1[2 * lane], sc1 = g_scale1[2 * lane + 1];
    const float sh0 = g_shift1[2 * lane], sh1 = g_shift1[2 * lane + 1];
    const float2* x1v = (const float2*)g_x1;

    float fk0[KPN], fk1[KPN];
#pragma unroll
    for (int k = 0; k < KPN; k++) { fk0[k] = 0.f; fk1[k] = 0.f; }

    for (int h = 0; h < NBH; h++) {
        unsigned mh = __shfl_sync(0xffffffffu, mask, h);
        if (!mh) continue;                                 /* warp-uniform */
        int jj = __shfl_sync(0xffffffffu, j, h);
        float2 v = x1v[(size_t)jj * 32 + lane];
        float a = v.x * sc0 + sh0; a = a > 0.f ? a : SLOPE * a;
        float b = v.y * sc1 + sh1; b = b > 0.f ? b : SLOPE * b;
        while (mh) {
            int k = __ffs(mh) - 1; mh &= mh - 1;
            float w = ws[warp][h][k];
            fk0[k] += w * a;
            fk1[k] += w * b;
        }
    }

    bf16* oh = g_fk_hi + (size_t)n * FKDIM;
    bf16* ol = g_fk_lo + (size_t)n * FKDIM;
#pragma unroll
    for (int k = 0; k < KPN; k++) {
        union { bf16 b[2]; uint32_t u; } H, L;
        bf16 h0 = __float2bfloat16(fk0[k]), h1 = __float2bfloat16(fk1[k]);
        H.b[0] = h0; H.b[1] = h1;
        L.b[0] = __float2bfloat16(fk0[k] - __bfloat162float(h0));
        L.b[1] = __float2bfloat16(fk1[k] - __bfloat162float(h1));
        *(uint32_t*)(oh + k * 64 + 2 * lane) = H.u;
        *(uint32_t*)(ol + k * 64 + 2 * lane) = L.u;
    }
}

/* ------------------------- final epilogue — known good ------------------- */
__global__ __launch_bounds__(256) void k_epilogue(float* __restrict__ out)
{
    __shared__ float s2[COUT], h2[COUT], ss[COUT], hs[COUT];
    const int t = threadIdx.x;
    s2[t] = g_scale2[t];  h2[t] = g_shift2[t];
    ss[t] = g_scalesc[t]; hs[t] = g_shiftsc[t];
    __syncthreads();

    const int idx = blockIdx.x * 256 + t;          /* float4 index */
    const int c4 = (idx & 63) * 4;

    float4 x = ((float4*)out)[idx];
    float4 s = ((const float4*)g_sc)[idx];
    float v0 = x.x * s2[c4 + 0] + h2[c4 + 0]; v0 = v0 > 0.f ? v0 : SLOPE * v0;
    float v1 = x.y * s2[c4 + 1] + h2[c4 + 1]; v1 = v1 > 0.f ? v1 : SLOPE * v1;
    float v2 = x.z * s2[c4 + 2] + h2[c4 + 2]; v2 = v2 > 0.f ? v2 : SLOPE * v2;
    float v3 = x.w * s2[c4 + 3] + h2[c4 + 3]; v3 = v3 > 0.f ? v3 : SLOPE * v3;
    float4 r;
    r.x = v0 + s.x * ss[c4 + 0] + hs[c4 + 0];
    r.y = v1 + s.y * ss[c4 + 1] + hs[c4 + 1];
    r.z = v2 + s.z * ss[c4 + 2] + hs[c4 + 2];
    r.w = v3 + s.w * ss[c4 + 3] + hs[c4 + 3];
    ((float4*)out)[idx] = r;
}

/* ------------------------- launch ---------------------------------------- */
extern "C" void kernel_launch(void* const* d_in, const int* in_sizes, int n_in,
                              void* d_out, int out_size)
{
    const float* feats = (const float*)d_in[0];
    const float* xyz   = (const float*)d_in[1];
    const int*   nidx  = (const int*)d_in[3];
    const float* W1    = (const float*)d_in[4];
    const float* g1    = (const float*)d_in[5];
    const float* b1    = (const float*)d_in[6];
    const float* kp    = (const float*)d_in[7];
    const float* kpw   = (const float*)d_in[8];
    const float* W2    = (const float*)d_in[9];
    const float* g2    = (const float*)d_in[10];
    const float* b2    = (const float*)d_in[11];
    const float* Wsc   = (const float*)d_in[12];
    const float* gsc   = (const float*)d_in[13];
    const float* bsc   = (const float*)d_in[14];
    float* out = (float*)d_out;

    static bool attr_done = false;
    if (!attr_done) {
        cudaFuncSetAttribute(k_gemm_u1, cudaFuncAttributeMaxDynamicSharedMemorySize, GEMM_SMEM);
        cudaFuncSetAttribute(k_gemm_sc, cudaFuncAttributeMaxDynamicSharedMemorySize, GEMM_SMEM);
        cudaFuncSetAttribute(k_gemm_fk, cudaFuncAttributeMaxDynamicSharedMemorySize, GEMM_SMEM);
        cudaFuncSetAttribute(k_gemm_u2, cudaFuncAttributeMaxDynamicSharedMemorySize, GEMM_SMEM);
        attr_done = true;
    }

    k_zero<<<1, 256>>>();
    k_prep_feats<<<(NPTS * CIN / 4) / 256, 256>>>(feats);
    k_prep_w<<<464, 256>>>(W1, Wsc, kpw, W2);

    /* unary1 + fused stats1 */
    k_gemm_u1<<<dim3(NPTS / 128, 1), 256, GEMM_SMEM>>>();
    /* shortcut + fused stats_sc */
    k_gemm_sc<<<dim3(NPTS / 128, 4), 256, GEMM_SMEM>>>();

    k_fin1 <<<1, D2>>>(g1, b1);
    k_finsc<<<1, COUT>>>(gsc, bsc);

    k_kpconv<<<NPTS / 8, 256>>>(xyz, nidx, kp);

    /* fk @ kpw -> xmid (bf16 split) */
    k_gemm_fk<<<dim3(NPTS / 128, 1), 256, GEMM_SMEM>>>();
    /* unary2 + fused stats2 */
    k_gemm_u2<<<dim3(NPTS / 128, 4), 256, GEMM_SMEM>>>(out);

    k_fin2<<<1, COUT>>>(g2, b2);

    k_epilogue<<<(NPTS * (COUT / 4)) / 256, 256>>>(out);
}